// round 11
// baseline (speedup 1.0000x reference)
#include <cuda_runtime.h>
#include <cuda_bf16.h>
#include <cstdint>

// ShiftedWindowAttention: mma.sync bf16-split GEMMs + SIMT attention.
// One CTA per 8x8 window. B=8, C=192, H=W=192, ws=8, ss=4, nh=6, hd=32, N=64.
// R10: m32n48 warp tiles (2x less fragment redundancy), B-fragments via direct
//      LDG from prepacked global (no smem weight staging), register softmax.

#define THREADS 512
#define NBLK    4608
#define CCH     192
#define HH      192
#define WWD     192

#define XP 200        // bf16 pitch for X/O planes (400B rows)
#define QP 36         // fp32 pitch for Q/K/V
#define SP 68         // fp32 pitch for scores
#define PJ 196        // fp32 pitch for proj result (aliases X planes)

// smem byte offsets
#define OFF_XH   0            // 64 x 200 bf16 = 25600 ; sPrj (64x196 f32) aliases XH/XL
#define OFF_XL   25600
#define OFF_S    51200        // scores 64 x 68 f32 = 17408
#define OFF_OH   68608        // attention-out hi plane
#define OFF_OL   94208
#define OFF_Q    119808       // 64 x 36 f32
#define OFF_K    129024
#define OFF_V    138240
#define OFF_TAB  147456       // 1350 f32
#define OFF_BIAS 152856       // 768 f32: qkv_b(576) | proj_b(192)
#define OFF_RID  155928       // 64 int
#define SMEM_BYTES 156192

// Prepacked B fragments: [plane hi/lo][stage][ks][nt][lane] -> uint2 = {b0,b1} regs.
// stages 0-5: qkv head h (96 outs); 6-7: proj halves (96 outs each).
__device__ uint2 gWB[2][8][12][12][32];

#define LDSM_X4(r, addr) \
    asm volatile("ldmatrix.sync.aligned.m8n8.x4.shared.b16 {%0,%1,%2,%3}, [%4];" \
        : "=r"((r)[0]), "=r"((r)[1]), "=r"((r)[2]), "=r"((r)[3]) : "r"(addr))
#define MMA_BF16(d, a, b0, b1) \
    asm volatile("mma.sync.aligned.m16n8k16.row.col.f32.bf16.bf16.f32 " \
        "{%0,%1,%2,%3}, {%4,%5,%6,%7}, {%8,%9}, {%0,%1,%2,%3};" \
        : "+f"((d)[0]), "+f"((d)[1]), "+f"((d)[2]), "+f"((d)[3]) \
        : "r"((a)[0]), "r"((a)[1]), "r"((a)[2]), "r"((a)[3]), "r"(b0), "r"(b1))

__device__ __forceinline__ uint32_t smem_u32(const void* p) {
    uint32_t a;
    asm("{ .reg .u64 t; cvta.to.shared.u64 t, %1; cvt.u32.u64 %0, t; }" : "=r"(a) : "l"(p));
    return a;
}
__device__ __forceinline__ uint32_t pk(float a, float b) {
    __nv_bfloat16 x = __float2bfloat16(a), y = __float2bfloat16(b);
    return (uint32_t)__bfloat16_as_ushort(x) | ((uint32_t)__bfloat16_as_ushort(y) << 16);
}

// ---- prepack: fp32 weights -> bf16 hi/lo B-fragment layout (once per launch) ----
__global__ void prepack_w(const float* __restrict__ qkv_w, const float* __restrict__ proj_w)
{
    int idx = blockIdx.x * 256 + threadIdx.x;
    if (idx >= 8 * 12 * 12 * 32) return;
    int lane = idx & 31;
    int q = idx >> 5;
    int nt = q % 12, ks = (q / 12) % 12, st = q / 144;
    int n  = nt * 8 + (lane >> 2);
    int kb = ks * 16 + (lane & 3) * 2;
    const float* src;
    if (st < 6) {
        int grow = (n >> 5) * 192 + st * 32 + (n & 31);
        src = qkv_w + grow * 192;
    } else {
        src = proj_w + ((st - 6) * 96 + n) * 192;
    }
    float w0 = src[kb], w1 = src[kb + 1], w2 = src[kb + 8], w3 = src[kb + 9];
    float h0 = __bfloat162float(__float2bfloat16(w0));
    float h1 = __bfloat162float(__float2bfloat16(w1));
    float h2 = __bfloat162float(__float2bfloat16(w2));
    float h3 = __bfloat162float(__float2bfloat16(w3));
    gWB[0][st][ks][nt][lane] = make_uint2(pk(w0, w1), pk(w2, w3));
    gWB[1][st][ks][nt][lane] = make_uint2(pk(w0 - h0, w1 - h1), pk(w2 - h2, w3 - h3));
}

__global__ void __launch_bounds__(THREADS, 1)
swin_mma(const float* __restrict__ x, const float* __restrict__ qkv_b,
         const float* __restrict__ proj_b, const float* __restrict__ tab,
         float* __restrict__ out)
{
    extern __shared__ char smb[];
    const uint32_t smu = smem_u32(smb);
    __nv_bfloat16* sXH = (__nv_bfloat16*)(smb + OFF_XH);
    __nv_bfloat16* sXL = (__nv_bfloat16*)(smb + OFF_XL);
    float* sQ   = (float*)(smb + OFF_Q);
    float* sK   = (float*)(smb + OFF_K);
    float* sV   = (float*)(smb + OFF_V);
    float* sS   = (float*)(smb + OFF_S);
    float* sPrj = (float*)(smb + OFF_XH);   // aliases X planes (X dead in proj phase)
    float* sTab = (float*)(smb + OFF_TAB);
    float* sBias= (float*)(smb + OFF_BIAS);
    int*   sReg = (int*)(smb + OFF_RID);

    const int tid = threadIdx.x, warp = tid >> 5, lane = tid & 31;
    const int r0 = warp * 4;

    const int b_ = blockIdx.x;
    const int bb = b_ / 576, win = b_ - bb * 576;
    const int wr = win / 24, wc = win - wr * 24;

    // ---- tables / bias / region ids ----
    for (int i = tid; i < 1350; i += THREADS) sTab[i] = tab[i];
    for (int i = tid; i < 768; i += THREADS) sBias[i] = (i < 576) ? qkv_b[i] : proj_b[i - 576];
    if (tid < 64) {
        int ii = tid >> 3, jj = tid & 7;
        int hs = wr * 8 + ii, ws = wc * 8 + jj;
        sReg[tid] = (hs < 184 ? 0 : (hs < 188 ? 1 : 2)) * 3 + (ws < 184 ? 0 : (ws < 188 ? 1 : 2));
    }

    // ---- gather shifted window -> X hi/lo bf16 planes ----
    const float* xb = x + (size_t)bb * CCH * HH * WWD;
    for (int e = tid; e < 64 * CCH; e += THREADS) {
        int c = e >> 6, r = e & 63;
        int hh2 = wr * 8 + (r >> 3) + 4; if (hh2 >= HH)  hh2 -= HH;
        int ww2 = wc * 8 + (r & 7) + 4;  if (ww2 >= WWD) ww2 -= WWD;
        float v = xb[(c * HH + hh2) * WWD + ww2];
        __nv_bfloat16 hi = __float2bfloat16(v);
        sXH[r * XP + c] = hi;
        sXL[r * XP + c] = __float2bfloat16(v - __bfloat162float(hi));
    }

    const float scale = 0.17677669529663687f;

    for (int h = 0; h < 6; h++) {
        __syncthreads();   // sQ/K/V free (prev head's SV done); gather visible on h=0

        // ---- QKV GEMM: 4 warps, m32n48 tiles, B-frags via LDG ----
        if (warp < 4) {
            const int mt = warp >> 1, ntg = warp & 1;
            const uint32_t aH = smu + OFF_XH + (mt * 32 + (lane & 15)) * 400 + ((lane >> 4) << 4);
            const uint32_t aL = aH + 25600;
            const uint2* __restrict__ bH = &gWB[0][h][0][ntg * 6][0] + lane;
            const uint2* __restrict__ bL = &gWB[1][h][0][ntg * 6][0] + lane;
            float acc[12][4] = {};
#pragma unroll
            for (int ks = 0; ks < 12; ks++) {
                uint32_t ah0[4], ah1[4], al0[4], al1[4];
                LDSM_X4(ah0, aH + ks * 32);
                LDSM_X4(ah1, aH + 6400 + ks * 32);
                LDSM_X4(al0, aL + ks * 32);
                LDSM_X4(al1, aL + 6400 + ks * 32);
#pragma unroll
                for (int t = 0; t < 6; t++) {
                    uint2 bh = bH[ks * 384 + t * 32];
                    uint2 bl = bL[ks * 384 + t * 32];
                    MMA_BF16(acc[t],     ah0, bh.x, bh.y);
                    MMA_BF16(acc[t],     ah0, bl.x, bl.y);
                    MMA_BF16(acc[t],     al0, bh.x, bh.y);
                    MMA_BF16(acc[6 + t], ah1, bh.x, bh.y);
                    MMA_BF16(acc[6 + t], ah1, bl.x, bl.y);
                    MMA_BF16(acc[6 + t], al1, bh.x, bh.y);
                }
            }
#pragma unroll
            for (int tt = 0; tt < 12; tt++) {
                const int tm = tt / 6, tn = tt - 6 * tm;
                int gc = (ntg * 6 + tn) * 8 + (lane & 3) * 2;
                int r  = mt * 32 + tm * 16 + (lane >> 2);
                float* dst; int lc; float b0_, b1_; float m = 1.f;
                if (gc < 32)      { dst = sQ; lc = gc;      b0_ = sBias[h*32+lc];     b1_ = sBias[h*32+lc+1];     m = scale; }
                else if (gc < 64) { dst = sK; lc = gc - 32; b0_ = sBias[192+h*32+lc]; b1_ = sBias[192+h*32+lc+1]; }
                else              { dst = sV; lc = gc - 64; b0_ = sBias[384+h*32+lc]; b1_ = sBias[384+h*32+lc+1]; }
                *(float2*)&dst[r * QP + lc]       = make_float2((acc[tt][0] + b0_) * m, (acc[tt][1] + b1_) * m);
                *(float2*)&dst[(r + 8) * QP + lc] = make_float2((acc[tt][2] + b0_) * m, (acc[tt][3] + b1_) * m);
            }
        }
        __syncthreads();

        // ---- scores (rows r0..r0+3, cols lane, lane+32) ----
        float sc[4][2];
#pragma unroll
        for (int i = 0; i < 4; i++) { sc[i][0] = 0.f; sc[i][1] = 0.f; }
#pragma unroll
        for (int d = 0; d < 32; d += 4) {
            float4 k0 = *(const float4*)&sK[lane * QP + d];
            float4 k1 = *(const float4*)&sK[(lane + 32) * QP + d];
#pragma unroll
            for (int i = 0; i < 4; i++) {
                float4 q = *(const float4*)&sQ[(r0 + i) * QP + d];
                sc[i][0] += q.x * k0.x + q.y * k0.y + q.z * k0.z + q.w * k0.w;
                sc[i][1] += q.x * k1.x + q.y * k1.y + q.z * k1.z + q.w * k1.w;
            }
        }

        // ---- bias + mask + register softmax (shfl reductions), write final P ----
#pragma unroll
        for (int i = 0; i < 4; i++) {
            int n = r0 + i;
            int i1 = n >> 3, j1 = n & 7;
            int rn = sReg[n];
            {
                int m2 = lane, i2 = m2 >> 3, j2 = m2 & 7;
                sc[i][0] += sTab[((i1 - i2 + 7) * 15 + (j1 - j2 + 7)) * 6 + h]
                          + ((sReg[m2] == rn) ? 0.f : -100.f);
            }
            {
                int m2 = lane + 32, i2 = m2 >> 3, j2 = m2 & 7;
                sc[i][1] += sTab[((i1 - i2 + 7) * 15 + (j1 - j2 + 7)) * 6 + h]
                          + ((sReg[m2] == rn) ? 0.f : -100.f);
            }
            float mx = fmaxf(sc[i][0], sc[i][1]);
            mx = fmaxf(mx, __shfl_xor_sync(0xffffffffu, mx, 16));
            mx = fmaxf(mx, __shfl_xor_sync(0xffffffffu, mx, 8));
            mx = fmaxf(mx, __shfl_xor_sync(0xffffffffu, mx, 4));
            mx = fmaxf(mx, __shfl_xor_sync(0xffffffffu, mx, 2));
            mx = fmaxf(mx, __shfl_xor_sync(0xffffffffu, mx, 1));
            float e0 = __expf(sc[i][0] - mx), e1 = __expf(sc[i][1] - mx);
            float sm = e0 + e1;
            sm += __shfl_xor_sync(0xffffffffu, sm, 16);
            sm += __shfl_xor_sync(0xffffffffu, sm, 8);
            sm += __shfl_xor_sync(0xffffffffu, sm, 4);
            sm += __shfl_xor_sync(0xffffffffu, sm, 2);
            sm += __shfl_xor_sync(0xffffffffu, sm, 1);
            float inv = 1.f / sm;
            sS[n * SP + lane]      = e0 * inv;
            sS[n * SP + lane + 32] = e1 * inv;
        }
        __syncwarp();

        // ---- O_h = P @ V -> O hi/lo planes (col h*32+lane) ----
        __nv_bfloat16* sOH = (__nv_bfloat16*)(smb + OFF_OH);
        __nv_bfloat16* sOL = (__nv_bfloat16*)(smb + OFF_OL);
        float oa[4] = {};
#pragma unroll
        for (int m2 = 0; m2 < 64; m2 += 4) {
            float v0 = sV[(m2 + 0) * QP + lane];
            float v1 = sV[(m2 + 1) * QP + lane];
            float v2 = sV[(m2 + 2) * QP + lane];
            float v3 = sV[(m2 + 3) * QP + lane];
#pragma unroll
            for (int i = 0; i < 4; i++) {
                float4 s = *(const float4*)&sS[(r0 + i) * SP + m2];
                oa[i] += s.x * v0 + s.y * v1 + s.z * v2 + s.w * v3;
            }
        }
#pragma unroll
        for (int i = 0; i < 4; i++) {
            int rr = r0 + i, cc = h * 32 + lane;
            __nv_bfloat16 hi = __float2bfloat16(oa[i]);
            sOH[rr * XP + cc] = hi;
            sOL[rr * XP + cc] = __float2bfloat16(oa[i] - __bfloat162float(hi));
        }
    }

    // ---- proj: 8 warps, m32n48 tiles over full N=192; X planes become sPrj ----
    __syncthreads();   // O planes complete; X dead
    if (warp < 8) {
        const int mt = warp >> 2, ntg = warp & 3;
        const int st = 6 + (ntg >> 1);
        const uint32_t aH = smu + OFF_OH + (mt * 32 + (lane & 15)) * 400 + ((lane >> 4) << 4);
        const uint32_t aL = aH + 25600;
        const uint2* __restrict__ bH = &gWB[0][st][0][(ntg & 1) * 6][0] + lane;
        const uint2* __restrict__ bL = &gWB[1][st][0][(ntg & 1) * 6][0] + lane;
        float acc[12][4] = {};
#pragma unroll
        for (int ks = 0; ks < 12; ks++) {
            uint32_t ah0[4], ah1[4], al0[4], al1[4];
            LDSM_X4(ah0, aH + ks * 32);
            LDSM_X4(ah1, aH + 6400 + ks * 32);
            LDSM_X4(al0, aL + ks * 32);
            LDSM_X4(al1, aL + 6400 + ks * 32);
#pragma unroll
            for (int t = 0; t < 6; t++) {
                uint2 bh = bH[ks * 384 + t * 32];
                uint2 bl = bL[ks * 384 + t * 32];
                MMA_BF16(acc[t],     ah0, bh.x, bh.y);
                MMA_BF16(acc[t],     ah0, bl.x, bl.y);
                MMA_BF16(acc[t],     al0, bh.x, bh.y);
                MMA_BF16(acc[6 + t], ah1, bh.x, bh.y);
                MMA_BF16(acc[6 + t], ah1, bl.x, bl.y);
                MMA_BF16(acc[6 + t], al1, bh.x, bh.y);
            }
        }
#pragma unroll
        for (int tt = 0; tt < 12; tt++) {
            const int tm = tt / 6, tn = tt - 6 * tm;
            int col = (ntg * 6 + tn) * 8 + (lane & 3) * 2;
            int r   = mt * 32 + tm * 16 + (lane >> 2);
            *(float2*)&sPrj[r * PJ + col]       = make_float2(acc[tt][0], acc[tt][1]);
            *(float2*)&sPrj[(r + 8) * PJ + col] = make_float2(acc[tt][2], acc[tt][3]);
        }
    }
    __syncthreads();

    // ---- scatter with reverse shift (+ proj bias) ----
    float* ob = out + (size_t)bb * CCH * HH * WWD;
    for (int e = tid; e < 64 * CCH; e += THREADS) {
        int c = e >> 6, r = e & 63;
        int hh2 = wr * 8 + (r >> 3) + 4; if (hh2 >= HH)  hh2 -= HH;
        int ww2 = wc * 8 + (r & 7) + 4;  if (ww2 >= WWD) ww2 -= WWD;
        ob[(c * HH + hh2) * WWD + ww2] = sPrj[r * PJ + c] + sBias[576 + c];
    }
}

extern "C" void kernel_launch(void* const* d_in, const int* in_sizes, int n_in,
                              void* d_out, int out_size)
{
    const float* x      = (const float*)d_in[0];
    const float* qkv_w  = (const float*)d_in[1];
    const float* qkv_b  = (const float*)d_in[2];
    const float* proj_w = (const float*)d_in[3];
    const float* proj_b = (const float*)d_in[4];
    const float* tab    = (const float*)d_in[5];
    float* out = (float*)d_out;

    prepack_w<<<144, 256>>>(qkv_w, proj_w);

    cudaFuncSetAttribute(swin_mma, cudaFuncAttributeMaxDynamicSharedMemorySize, SMEM_BYTES);
    swin_mma<<<NBLK, THREADS, SMEM_BYTES>>>(x, qkv_b, proj_b, tab, out);
}

// round 12
// speedup vs baseline: 1.2118x; 1.2118x over previous
#include <cuda_runtime.h>
#include <cuda_bf16.h>
#include <cstdint>

// ShiftedWindowAttention: mma.sync bf16-split GEMMs + SIMT attention.
// One CTA per 8x8 window. B=8, C=192, H=W=192, ws=8, ss=4, nh=6, hd=32, N=64.
// R11: R9's 16-warp m16n24 GEMM tiling + R10's LDG B-fragments (no smem weight
//      staging) + register softmax + single-pass proj (acc[6][4]).

#define THREADS 512
#define NBLK    4608
#define CCH     192
#define HH      192
#define WWD     192

#define XP 200        // bf16 pitch for X/O planes (400B rows)
#define QP 36         // fp32 pitch for Q/K/V
#define SP 68         // fp32 pitch for scores
#define PJ 196        // fp32 pitch for proj result (aliases X planes)

// smem byte offsets
#define OFF_XH   0            // 64 x 200 bf16 = 25600 ; sPrj (64x196 f32) aliases XH/XL
#define OFF_XL   25600
#define OFF_S    51200        // scores 64 x 68 f32 = 17408
#define OFF_OH   68608        // attention-out hi plane
#define OFF_OL   94208
#define OFF_Q    119808       // 64 x 36 f32
#define OFF_K    129024
#define OFF_V    138240
#define OFF_TAB  147456       // 1350 f32
#define OFF_BIAS 152856       // 768 f32: qkv_b(576) | proj_b(192)
#define OFF_RID  155928       // 64 int
#define SMEM_BYTES 156192

// Prepacked B fragments: [plane hi/lo][stage][ks][nt][lane] -> uint2 = {b0,b1} regs.
// stages 0-5: qkv head h (96 outs); 6-7: proj halves (96 outs each).
__device__ uint2 gWB[2][8][12][12][32];

#define LDSM_X4(r, addr) \
    asm volatile("ldmatrix.sync.aligned.m8n8.x4.shared.b16 {%0,%1,%2,%3}, [%4];" \
        : "=r"((r)[0]), "=r"((r)[1]), "=r"((r)[2]), "=r"((r)[3]) : "r"(addr))
#define MMA_BF16(d, a, b0, b1) \
    asm volatile("mma.sync.aligned.m16n8k16.row.col.f32.bf16.bf16.f32 " \
        "{%0,%1,%2,%3}, {%4,%5,%6,%7}, {%8,%9}, {%0,%1,%2,%3};" \
        : "+f"((d)[0]), "+f"((d)[1]), "+f"((d)[2]), "+f"((d)[3]) \
        : "r"((a)[0]), "r"((a)[1]), "r"((a)[2]), "r"((a)[3]), "r"(b0), "r"(b1))

__device__ __forceinline__ uint32_t smem_u32(const void* p) {
    uint32_t a;
    asm("{ .reg .u64 t; cvta.to.shared.u64 t, %1; cvt.u32.u64 %0, t; }" : "=r"(a) : "l"(p));
    return a;
}
__device__ __forceinline__ uint32_t pk(float a, float b) {
    __nv_bfloat16 x = __float2bfloat16(a), y = __float2bfloat16(b);
    return (uint32_t)__bfloat16_as_ushort(x) | ((uint32_t)__bfloat16_as_ushort(y) << 16);
}

// ---- prepack: fp32 weights -> bf16 hi/lo B-fragment layout (once per launch) ----
__global__ void prepack_w(const float* __restrict__ qkv_w, const float* __restrict__ proj_w)
{
    int idx = blockIdx.x * 256 + threadIdx.x;
    if (idx >= 8 * 12 * 12 * 32) return;
    int lane = idx & 31;
    int q = idx >> 5;
    int nt = q % 12, ks = (q / 12) % 12, st = q / 144;
    int n  = nt * 8 + (lane >> 2);
    int kb = ks * 16 + (lane & 3) * 2;
    const float* src;
    if (st < 6) {
        int grow = (n >> 5) * 192 + st * 32 + (n & 31);
        src = qkv_w + grow * 192;
    } else {
        src = proj_w + ((st - 6) * 96 + n) * 192;
    }
    float w0 = src[kb], w1 = src[kb + 1], w2 = src[kb + 8], w3 = src[kb + 9];
    float h0 = __bfloat162float(__float2bfloat16(w0));
    float h1 = __bfloat162float(__float2bfloat16(w1));
    float h2 = __bfloat162float(__float2bfloat16(w2));
    float h3 = __bfloat162float(__float2bfloat16(w3));
    gWB[0][st][ks][nt][lane] = make_uint2(pk(w0, w1), pk(w2, w3));
    gWB[1][st][ks][nt][lane] = make_uint2(pk(w0 - h0, w1 - h1), pk(w2 - h2, w3 - h3));
}

__global__ void __launch_bounds__(THREADS, 1)
swin_mma(const float* __restrict__ x, const float* __restrict__ qkv_b,
         const float* __restrict__ proj_b, const float* __restrict__ tab,
         float* __restrict__ out)
{
    extern __shared__ char smb[];
    const uint32_t smu = smem_u32(smb);
    __nv_bfloat16* sXH = (__nv_bfloat16*)(smb + OFF_XH);
    __nv_bfloat16* sXL = (__nv_bfloat16*)(smb + OFF_XL);
    __nv_bfloat16* sOH = (__nv_bfloat16*)(smb + OFF_OH);
    __nv_bfloat16* sOL = (__nv_bfloat16*)(smb + OFF_OL);
    float* sQ   = (float*)(smb + OFF_Q);
    float* sK   = (float*)(smb + OFF_K);
    float* sV   = (float*)(smb + OFF_V);
    float* sS   = (float*)(smb + OFF_S);
    float* sPrj = (float*)(smb + OFF_XH);   // aliases X planes (X dead in proj phase)
    float* sTab = (float*)(smb + OFF_TAB);
    float* sBias= (float*)(smb + OFF_BIAS);
    int*   sReg = (int*)(smb + OFF_RID);

    const int tid = threadIdx.x, warp = tid >> 5, lane = tid & 31;
    const int mt = warp & 3, ntg = warp >> 2;   // GEMM tiling: 4 m-tiles x 4 n-groups
    const int r0 = warp * 4;                    // attention rows

    const int b_ = blockIdx.x;
    const int bb = b_ / 576, win = b_ - bb * 576;
    const int wr = win / 24, wc = win - wr * 24;

    const uint2* __restrict__ gW0 = &gWB[0][0][0][0][0];
    const uint2* __restrict__ gW1 = &gWB[1][0][0][0][0];

    // ldmatrix A base addresses (m16 tile mt)
    const uint32_t aXH = smu + OFF_XH + (mt * 16 + (lane & 15)) * 400 + ((lane >> 4) << 4);
    const uint32_t aXL = aXH + 25600;
    const uint32_t aOH = smu + OFF_OH + (mt * 16 + (lane & 15)) * 400 + ((lane >> 4) << 4);
    const uint32_t aOL = aOH + 25600;

    // ---- tables / bias / region ids ----
    for (int i = tid; i < 1350; i += THREADS) sTab[i] = tab[i];
    for (int i = tid; i < 768; i += THREADS) sBias[i] = (i < 576) ? qkv_b[i] : proj_b[i - 576];
    if (tid < 64) {
        int ii = tid >> 3, jj = tid & 7;
        int hs = wr * 8 + ii, ws = wc * 8 + jj;
        sReg[tid] = (hs < 184 ? 0 : (hs < 188 ? 1 : 2)) * 3 + (ws < 184 ? 0 : (ws < 188 ? 1 : 2));
    }

    // ---- gather shifted window -> X hi/lo bf16 planes ----
    const float* xb = x + (size_t)bb * CCH * HH * WWD;
    for (int e = tid; e < 64 * CCH; e += THREADS) {
        int c = e >> 6, r = e & 63;
        int hh2 = wr * 8 + (r >> 3) + 4; if (hh2 >= HH)  hh2 -= HH;
        int ww2 = wc * 8 + (r & 7) + 4;  if (ww2 >= WWD) ww2 -= WWD;
        float v = xb[(c * HH + hh2) * WWD + ww2];
        __nv_bfloat16 hi = __float2bfloat16(v);
        sXH[r * XP + c] = hi;
        sXL[r * XP + c] = __float2bfloat16(v - __bfloat162float(hi));
    }

    const float scale = 0.17677669529663687f;

    for (int h = 0; h < 6; h++) {
        __syncthreads();   // sQ/K/V free (prev head's SV done); gather visible on h=0

        // ---- QKV GEMM: 16 warps, m16n24 tiles, B-frags via LDG ----
        {
            const int bbase = h * 4608 + (3 * ntg) * 32 + lane;   // [st][ks][nt][lane]
            float acc[3][4] = {};
#pragma unroll
            for (int ks = 0; ks < 12; ks++) {
                uint32_t ah[4], al[4];
                LDSM_X4(ah, aXH + ks * 32);
                LDSM_X4(al, aXL + ks * 32);
#pragma unroll
                for (int t = 0; t < 3; t++) {
                    uint2 bh = gW0[bbase + ks * 384 + t * 32];
                    uint2 bl = gW1[bbase + ks * 384 + t * 32];
                    MMA_BF16(acc[t], ah, bh.x, bh.y);
                    MMA_BF16(acc[t], ah, bl.x, bl.y);
                    MMA_BF16(acc[t], al, bh.x, bh.y);
                }
            }
#pragma unroll
            for (int t = 0; t < 3; t++) {
                int gc = (3 * ntg + t) * 8 + (lane & 3) * 2;
                int r  = mt * 16 + (lane >> 2);
                float* dst; int lc; float b0_, b1_; float m = 1.f;
                if (gc < 32)      { dst = sQ; lc = gc;      b0_ = sBias[h*32+lc];     b1_ = sBias[h*32+lc+1];     m = scale; }
                else if (gc < 64) { dst = sK; lc = gc - 32; b0_ = sBias[192+h*32+lc]; b1_ = sBias[192+h*32+lc+1]; }
                else              { dst = sV; lc = gc - 64; b0_ = sBias[384+h*32+lc]; b1_ = sBias[384+h*32+lc+1]; }
                *(float2*)&dst[r * QP + lc]       = make_float2((acc[t][0] + b0_) * m, (acc[t][1] + b1_) * m);
                *(float2*)&dst[(r + 8) * QP + lc] = make_float2((acc[t][2] + b0_) * m, (acc[t][3] + b1_) * m);
            }
        }
        __syncthreads();

        // ---- scores (rows r0..r0+3, cols lane, lane+32) ----
        float sc[4][2];
#pragma unroll
        for (int i = 0; i < 4; i++) { sc[i][0] = 0.f; sc[i][1] = 0.f; }
#pragma unroll
        for (int d = 0; d < 32; d += 4) {
            float4 k0 = *(const float4*)&sK[lane * QP + d];
            float4 k1 = *(const float4*)&sK[(lane + 32) * QP + d];
#pragma unroll
            for (int i = 0; i < 4; i++) {
                float4 q = *(const float4*)&sQ[(r0 + i) * QP + d];
                sc[i][0] += q.x * k0.x + q.y * k0.y + q.z * k0.z + q.w * k0.w;
                sc[i][1] += q.x * k1.x + q.y * k1.y + q.z * k1.z + q.w * k1.w;
            }
        }

        // ---- bias + mask + register softmax (shfl reductions), write final P ----
#pragma unroll
        for (int i = 0; i < 4; i++) {
            int n = r0 + i;
            int i1 = n >> 3, j1 = n & 7;
            int rn = sReg[n];
            {
                int m2 = lane, i2 = m2 >> 3, j2 = m2 & 7;
                sc[i][0] += sTab[((i1 - i2 + 7) * 15 + (j1 - j2 + 7)) * 6 + h]
                          + ((sReg[m2] == rn) ? 0.f : -100.f);
            }
            {
                int m2 = lane + 32, i2 = m2 >> 3, j2 = m2 & 7;
                sc[i][1] += sTab[((i1 - i2 + 7) * 15 + (j1 - j2 + 7)) * 6 + h]
                          + ((sReg[m2] == rn) ? 0.f : -100.f);
            }
            float mx = fmaxf(sc[i][0], sc[i][1]);
            mx = fmaxf(mx, __shfl_xor_sync(0xffffffffu, mx, 16));
            mx = fmaxf(mx, __shfl_xor_sync(0xffffffffu, mx, 8));
            mx = fmaxf(mx, __shfl_xor_sync(0xffffffffu, mx, 4));
            mx = fmaxf(mx, __shfl_xor_sync(0xffffffffu, mx, 2));
            mx = fmaxf(mx, __shfl_xor_sync(0xffffffffu, mx, 1));
            float e0 = __expf(sc[i][0] - mx), e1 = __expf(sc[i][1] - mx);
            float sm = e0 + e1;
            sm += __shfl_xor_sync(0xffffffffu, sm, 16);
            sm += __shfl_xor_sync(0xffffffffu, sm, 8);
            sm += __shfl_xor_sync(0xffffffffu, sm, 4);
            sm += __shfl_xor_sync(0xffffffffu, sm, 2);
            sm += __shfl_xor_sync(0xffffffffu, sm, 1);
            float inv = 1.f / sm;
            sS[n * SP + lane]      = e0 * inv;
            sS[n * SP + lane + 32] = e1 * inv;
        }
        __syncwarp();

        // ---- O_h = P @ V -> O hi/lo planes (col h*32+lane) ----
        float oa[4] = {};
#pragma unroll
        for (int m2 = 0; m2 < 64; m2 += 4) {
            float v0 = sV[(m2 + 0) * QP + lane];
            float v1 = sV[(m2 + 1) * QP + lane];
            float v2 = sV[(m2 + 2) * QP + lane];
            float v3 = sV[(m2 + 3) * QP + lane];
#pragma unroll
            for (int i = 0; i < 4; i++) {
                float4 s = *(const float4*)&sS[(r0 + i) * SP + m2];
                oa[i] += s.x * v0 + s.y * v1 + s.z * v2 + s.w * v3;
            }
        }
#pragma unroll
        for (int i = 0; i < 4; i++) {
            int rr = r0 + i, cc = h * 32 + lane;
            __nv_bfloat16 hi = __float2bfloat16(oa[i]);
            sOH[rr * XP + cc] = hi;
            sOL[rr * XP + cc] = __float2bfloat16(oa[i] - __bfloat162float(hi));
        }
    }

    // ---- proj: single pass, 16 warps, m16 x n48 (6 n-tiles spanning stages 6/7) ----
    __syncthreads();   // O planes complete; X dead -> sPrj
    {
        int boff[6];
#pragma unroll
        for (int t = 0; t < 6; t++) {
            int idx = ntg * 6 + t;                 // global n-tile 0..23
            int st  = 6 + (idx >= 12);
            int nt  = idx - 12 * (idx >= 12);
            boff[t] = st * 4608 + nt * 32 + lane;
        }
        float acc[6][4] = {};
#pragma unroll
        for (int ks = 0; ks < 12; ks++) {
            uint32_t ah[4], al[4];
            LDSM_X4(ah, aOH + ks * 32);
            LDSM_X4(al, aOL + ks * 32);
#pragma unroll
            for (int t = 0; t < 6; t++) {
                uint2 bh = gW0[boff[t] + ks * 384];
                uint2 bl = gW1[boff[t] + ks * 384];
                MMA_BF16(acc[t], ah, bh.x, bh.y);
                MMA_BF16(acc[t], ah, bl.x, bl.y);
                MMA_BF16(acc[t], al, bh.x, bh.y);
            }
        }
#pragma unroll
        for (int t = 0; t < 6; t++) {
            int col = (ntg * 6 + t) * 8 + (lane & 3) * 2;
            int r   = mt * 16 + (lane >> 2);
            *(float2*)&sPrj[r * PJ + col]       = make_float2(acc[t][0], acc[t][1]);
            *(float2*)&sPrj[(r + 8) * PJ + col] = make_float2(acc[t][2], acc[t][3]);
        }
    }
    __syncthreads();

    // ---- scatter with reverse shift (+ proj bias) ----
    float* ob = out + (size_t)bb * CCH * HH * WWD;
    for (int e = tid; e < 64 * CCH; e += THREADS) {
        int c = e >> 6, r = e & 63;
        int hh2 = wr * 8 + (r >> 3) + 4; if (hh2 >= HH)  hh2 -= HH;
        int ww2 = wc * 8 + (r & 7) + 4;  if (ww2 >= WWD) ww2 -= WWD;
        ob[(c * HH + hh2) * WWD + ww2] = sPrj[r * PJ + c] + sBias[576 + c];
    }
}

extern "C" void kernel_launch(void* const* d_in, const int* in_sizes, int n_in,
                              void* d_out, int out_size)
{
    const float* x      = (const float*)d_in[0];
    const float* qkv_w  = (const float*)d_in[1];
    const float* qkv_b  = (const float*)d_in[2];
    const float* proj_w = (const float*)d_in[3];
    const float* proj_b = (const float*)d_in[4];
    const float* tab    = (const float*)d_in[5];
    float* out = (float*)d_out;

    prepack_w<<<144, 256>>>(qkv_w, proj_w);

    cudaFuncSetAttribute(swin_mma, cudaFuncAttributeMaxDynamicSharedMemorySize, SMEM_BYTES);
    swin_mma<<<NBLK, THREADS, SMEM_BYTES>>>(x, qkv_b, proj_b, tab, out);
}

// round 13
// speedup vs baseline: 1.6298x; 1.3449x over previous
#include <cuda_runtime.h>
#include <cuda_bf16.h>
#include <cstdint>

// ShiftedWindowAttention: fully tensor-core (mma.sync bf16-split) incl. attention.
// One CTA per 8x8 window. B=8, C=192, H=W=192, ws=8, ss=4, nh=6, hd=32, N=64.
// R12: QK^T and P@V on mma.sync (frag softmax, P/V bf16-split), uint4 B-frag LDG.

#define THREADS 512
#define NBLK    4608
#define CCH     192
#define HH      192
#define WWD     192

#define XP 200        // bf16 pitch for X/O planes (400B rows)
#define PJ 196        // fp32 pitch for proj result (aliases X planes)

// smem byte offsets
#define OFF_XH   0            // 64 x 200 bf16 = 25600 ; sPrj aliases XH/XL
#define OFF_XL   25600
#define OFF_OH   51200
#define OFF_OL   76800
#define OFF_QH   102400       // Q/K/V bf16 planes: 64 rows x 80B (pitch 40 bf16)
#define OFF_QL   107520
#define OFF_KH   112640
#define OFF_KL   117760
#define OFF_VH   122880
#define OFF_VL   128000
#define OFF_PH   133120       // P planes: 64 rows x 144B (pitch 72 bf16)
#define OFF_PL   142336
#define OFF_RM   151552       // 4 x 64 f32 row-max partials
#define OFF_RS   152576       // 4 x 64 f32 row-sum partials
#define OFF_TAB  153600       // 1350 f32
#define OFF_BIAS 159008       // 768 f32: qkv_b(576) | proj_b(192)
#define OFF_RID  162080       // 64 int
#define SMEM_BYTES 162368

// Prepacked B fragments: [stage][ks][nt][lane] -> uint4 {bh0,bh1,bl0,bl1}.
__device__ uint4 gWB[8][12][12][32];

#define LDSM_X4(r, addr) \
    asm volatile("ldmatrix.sync.aligned.m8n8.x4.shared.b16 {%0,%1,%2,%3}, [%4];" \
        : "=r"((r)[0]), "=r"((r)[1]), "=r"((r)[2]), "=r"((r)[3]) : "r"(addr))
#define LDSM_X2(r, addr) \
    asm volatile("ldmatrix.sync.aligned.m8n8.x2.shared.b16 {%0,%1}, [%2];" \
        : "=r"((r)[0]), "=r"((r)[1]) : "r"(addr))
#define LDSM_X2T(r, addr) \
    asm volatile("ldmatrix.sync.aligned.m8n8.x2.trans.shared.b16 {%0,%1}, [%2];" \
        : "=r"((r)[0]), "=r"((r)[1]) : "r"(addr))
#define MMA_BF16(d, a, b0, b1) \
    asm volatile("mma.sync.aligned.m16n8k16.row.col.f32.bf16.bf16.f32 " \
        "{%0,%1,%2,%3}, {%4,%5,%6,%7}, {%8,%9}, {%0,%1,%2,%3};" \
        : "+f"((d)[0]), "+f"((d)[1]), "+f"((d)[2]), "+f"((d)[3]) \
        : "r"((a)[0]), "r"((a)[1]), "r"((a)[2]), "r"((a)[3]), "r"(b0), "r"(b1))

__device__ __forceinline__ uint32_t smem_u32(const void* p) {
    uint32_t a;
    asm("{ .reg .u64 t; cvta.to.shared.u64 t, %1; cvt.u32.u64 %0, t; }" : "=r"(a) : "l"(p));
    return a;
}
__device__ __forceinline__ uint32_t pk(float a, float b) {
    __nv_bfloat16 x = __float2bfloat16(a), y = __float2bfloat16(b);
    return (uint32_t)__bfloat16_as_ushort(x) | ((uint32_t)__bfloat16_as_ushort(y) << 16);
}
__device__ __forceinline__ void split2(float a, float b, uint32_t& hw, uint32_t& lw) {
    __nv_bfloat16 ha = __float2bfloat16(a), hb = __float2bfloat16(b);
    hw = (uint32_t)__bfloat16_as_ushort(ha) | ((uint32_t)__bfloat16_as_ushort(hb) << 16);
    lw = pk(a - __bfloat162float(ha), b - __bfloat162float(hb));
}

// ---- prepack: fp32 weights -> bf16 hi/lo B-fragment layout (once per launch) ----
__global__ void prepack_w(const float* __restrict__ qkv_w, const float* __restrict__ proj_w)
{
    int idx = blockIdx.x * 256 + threadIdx.x;
    if (idx >= 8 * 12 * 12 * 32) return;
    int lane = idx & 31;
    int q = idx >> 5;
    int nt = q % 12, ks = (q / 12) % 12, st = q / 144;
    int n  = nt * 8 + (lane >> 2);
    int kb = ks * 16 + (lane & 3) * 2;
    const float* src;
    if (st < 6) {
        int grow = (n >> 5) * 192 + st * 32 + (n & 31);
        src = qkv_w + grow * 192;
    } else {
        src = proj_w + ((st - 6) * 96 + n) * 192;
    }
    float w0 = src[kb], w1 = src[kb + 1], w2 = src[kb + 8], w3 = src[kb + 9];
    float h0 = __bfloat162float(__float2bfloat16(w0));
    float h1 = __bfloat162float(__float2bfloat16(w1));
    float h2 = __bfloat162float(__float2bfloat16(w2));
    float h3 = __bfloat162float(__float2bfloat16(w3));
    gWB[st][ks][nt][lane] = make_uint4(pk(w0, w1), pk(w2, w3),
                                       pk(w0 - h0, w1 - h1), pk(w2 - h2, w3 - h3));
}

__global__ void __launch_bounds__(THREADS, 1)
swin_mma(const float* __restrict__ x, const float* __restrict__ qkv_b,
         const float* __restrict__ proj_b, const float* __restrict__ tab,
         float* __restrict__ out)
{
    extern __shared__ char smb[];
    const uint32_t smu = smem_u32(smb);
    __nv_bfloat16* sXH = (__nv_bfloat16*)(smb + OFF_XH);
    __nv_bfloat16* sXL = (__nv_bfloat16*)(smb + OFF_XL);
    float* sPrj = (float*)(smb + OFF_XH);
    float* sRM  = (float*)(smb + OFF_RM);
    float* sRS  = (float*)(smb + OFF_RS);
    float* sTab = (float*)(smb + OFF_TAB);
    float* sBias= (float*)(smb + OFF_BIAS);
    int*   sReg = (int*)(smb + OFF_RID);

    const int tid = threadIdx.x, warp = tid >> 5, lane = tid & 31;
    const int mt = warp & 3, ntg = warp >> 2;

    const int b_ = blockIdx.x;
    const int bb = b_ / 576, win = b_ - bb * 576;
    const int wr = win / 24, wc = win - wr * 24;

    const uint4* __restrict__ gW = &gWB[0][0][0][0];

    // A-frag ldmatrix bases
    const uint32_t aXH = smu + OFF_XH + (mt * 16 + (lane & 15)) * 400 + ((lane >> 4) << 4);
    const uint32_t aXL = aXH + 25600;
    const uint32_t aOH = smu + OFF_OH + (mt * 16 + (lane & 15)) * 400 + ((lane >> 4) << 4);
    const uint32_t aOL = aOH + 25600;
    const uint32_t aQH = smu + OFF_QH + (mt * 16 + (lane & 15)) * 80 + ((lane >> 4) << 4);
    const uint32_t aQL = aQH + 5120;
    const uint32_t aKH = smu + OFF_KH + (lane & 7) * 80 + (((lane >> 3) & 1) << 4);
    const uint32_t aKL = aKH + 5120;
    const uint32_t aPH = smu + OFF_PH + (mt * 16 + (lane & 15)) * 144 + ((lane >> 4) << 4);
    const uint32_t aPL = aPH + 9216;
    const uint32_t aVH = smu + OFF_VH + (lane & 15) * 80 + ntg * 16;
    const uint32_t aVL = aVH + 5120;

    // ---- tables / bias / region ids ----
    for (int i = tid; i < 1350; i += THREADS) sTab[i] = tab[i];
    for (int i = tid; i < 768; i += THREADS) sBias[i] = (i < 576) ? qkv_b[i] : proj_b[i - 576];
    if (tid < 64) {
        int ii = tid >> 3, jj = tid & 7;
        int hs = wr * 8 + ii, ws = wc * 8 + jj;
        sReg[tid] = (hs < 184 ? 0 : (hs < 188 ? 1 : 2)) * 3 + (ws < 184 ? 0 : (ws < 188 ? 1 : 2));
    }

    // ---- gather shifted window -> X hi/lo bf16 planes ----
    const float* xb = x + (size_t)bb * CCH * HH * WWD;
    for (int e = tid; e < 64 * CCH; e += THREADS) {
        int c = e >> 6, r = e & 63;
        int hh2 = wr * 8 + (r >> 3) + 4; if (hh2 >= HH)  hh2 -= HH;
        int ww2 = wc * 8 + (r & 7) + 4;  if (ww2 >= WWD) ww2 -= WWD;
        float v = xb[(c * HH + hh2) * WWD + ww2];
        __nv_bfloat16 hi = __float2bfloat16(v);
        sXH[r * XP + c] = hi;
        sXL[r * XP + c] = __float2bfloat16(v - __bfloat162float(hi));
    }

    const float scale = 0.17677669529663687f;
    const int rA = mt * 16 + (lane >> 2), rB = rA + 8;

    for (int h = 0; h < 6; h++) {
        __syncthreads();   // QKV/P planes free for rewrite; gather visible at h=0

        // ---- QKV GEMM: 16 warps m16n24, B-frags via uint4 LDG ----
        {
            const uint4* bw = gW + h * 4608 + (3 * ntg) * 32 + lane;
            float acc[3][4] = {};
#pragma unroll
            for (int ks = 0; ks < 12; ks++) {
                uint32_t ah[4], al[4];
                LDSM_X4(ah, aXH + ks * 32);
                LDSM_X4(al, aXL + ks * 32);
#pragma unroll
                for (int t = 0; t < 3; t++) {
                    uint4 b = bw[ks * 384 + t * 32];
                    MMA_BF16(acc[t], ah, b.x, b.y);
                    MMA_BF16(acc[t], ah, b.z, b.w);
                    MMA_BF16(acc[t], al, b.x, b.y);
                }
            }
#pragma unroll
            for (int t = 0; t < 3; t++) {
                int gc = (3 * ntg + t) * 8 + (lane & 3) * 2;
                uint32_t base; int lc; float b0_, b1_; float m = 1.f;
                if (gc < 32)      { base = smu + OFF_QH; lc = gc;      b0_ = sBias[h*32+lc];     b1_ = sBias[h*32+lc+1];     m = scale; }
                else if (gc < 64) { base = smu + OFF_KH; lc = gc - 32; b0_ = sBias[192+h*32+lc]; b1_ = sBias[192+h*32+lc+1]; }
                else              { base = smu + OFF_VH; lc = gc - 64; b0_ = sBias[384+h*32+lc]; b1_ = sBias[384+h*32+lc+1]; }
                uint32_t hw, lw;
                split2((acc[t][0] + b0_) * m, (acc[t][1] + b1_) * m, hw, lw);
                *(uint32_t*)(smb + (base - smu) + rA * 80 + lc * 2) = hw;
                *(uint32_t*)(smb + (base - smu) + 5120 + rA * 80 + lc * 2) = lw;
                split2((acc[t][2] + b0_) * m, (acc[t][3] + b1_) * m, hw, lw);
                *(uint32_t*)(smb + (base - smu) + rB * 80 + lc * 2) = hw;
                *(uint32_t*)(smb + (base - smu) + 5120 + rB * 80 + lc * 2) = lw;
            }
        }
        __syncthreads();

        // ---- scores: warp tile m16 x n16 (tiles ntg*2, ntg*2+1) ----
        float cs[2][4] = {};
#pragma unroll
        for (int ks = 0; ks < 2; ks++) {
            uint32_t qh[4], ql[4];
            LDSM_X4(qh, aQH + ks * 32);
            LDSM_X4(ql, aQL + ks * 32);
#pragma unroll
            for (int t = 0; t < 2; t++) {
                uint32_t kh[2], kl[2];
                LDSM_X2(kh, aKH + (ntg * 2 + t) * 640 + ks * 32);
                LDSM_X2(kl, aKL + (ntg * 2 + t) * 640 + ks * 32);
                MMA_BF16(cs[t], qh, kh[0], kh[1]);
                MMA_BF16(cs[t], qh, kl[0], kl[1]);
                MMA_BF16(cs[t], ql, kh[0], kh[1]);
            }
        }

        // ---- bias + mask on fragments ----
        {
            int regA = sReg[rA], regB = sReg[rB];
            int i1A = rA >> 3, j1A = rA & 7, i1B = rB >> 3, j1B = rB & 7;
#pragma unroll
            for (int t = 0; t < 2; t++) {
#pragma unroll
                for (int par = 0; par < 2; par++) {
                    int m = ntg * 16 + t * 8 + (lane & 3) * 2 + par;
                    int i2 = m >> 3, j2 = m & 7, rm = sReg[m];
                    cs[t][par]     += sTab[((i1A - i2 + 7) * 15 + (j1A - j2 + 7)) * 6 + h]
                                    + (rm == regA ? 0.f : -100.f);
                    cs[t][2 + par] += sTab[((i1B - i2 + 7) * 15 + (j1B - j2 + 7)) * 6 + h]
                                    + (rm == regB ? 0.f : -100.f);
                }
            }
        }

        // ---- softmax on fragments (quad shfl + cross-warp smem) ----
        {
            float mA = fmaxf(fmaxf(cs[0][0], cs[0][1]), fmaxf(cs[1][0], cs[1][1]));
            float mB = fmaxf(fmaxf(cs[0][2], cs[0][3]), fmaxf(cs[1][2], cs[1][3]));
            mA = fmaxf(mA, __shfl_xor_sync(0xffffffffu, mA, 1));
            mA = fmaxf(mA, __shfl_xor_sync(0xffffffffu, mA, 2));
            mB = fmaxf(mB, __shfl_xor_sync(0xffffffffu, mB, 1));
            mB = fmaxf(mB, __shfl_xor_sync(0xffffffffu, mB, 2));
            if ((lane & 3) == 0) { sRM[ntg * 64 + rA] = mA; sRM[ntg * 64 + rB] = mB; }
        }
        __syncthreads();
        float invA, invB;
        {
            float gA = fmaxf(fmaxf(sRM[rA], sRM[64 + rA]), fmaxf(sRM[128 + rA], sRM[192 + rA]));
            float gB = fmaxf(fmaxf(sRM[rB], sRM[64 + rB]), fmaxf(sRM[128 + rB], sRM[192 + rB]));
#pragma unroll
            for (int t = 0; t < 2; t++) {
                cs[t][0] = __expf(cs[t][0] - gA); cs[t][1] = __expf(cs[t][1] - gA);
                cs[t][2] = __expf(cs[t][2] - gB); cs[t][3] = __expf(cs[t][3] - gB);
            }
            float sA = cs[0][0] + cs[0][1] + cs[1][0] + cs[1][1];
            float sB = cs[0][2] + cs[0][3] + cs[1][2] + cs[1][3];
            sA += __shfl_xor_sync(0xffffffffu, sA, 1);
            sA += __shfl_xor_sync(0xffffffffu, sA, 2);
            sB += __shfl_xor_sync(0xffffffffu, sB, 1);
            sB += __shfl_xor_sync(0xffffffffu, sB, 2);
            if ((lane & 3) == 0) { sRS[ntg * 64 + rA] = sA; sRS[ntg * 64 + rB] = sB; }
            __syncthreads();
            invA = 1.f / (sRS[rA] + sRS[64 + rA] + sRS[128 + rA] + sRS[192 + rA]);
            invB = 1.f / (sRS[rB] + sRS[64 + rB] + sRS[128 + rB] + sRS[192 + rB]);
        }

        // ---- write P hi/lo planes ----
#pragma unroll
        for (int t = 0; t < 2; t++) {
            int cb = (ntg * 16 + t * 8 + (lane & 3) * 2) * 2;
            uint32_t hw, lw;
            split2(cs[t][0] * invA, cs[t][1] * invA, hw, lw);
            *(uint32_t*)(smb + OFF_PH + rA * 144 + cb) = hw;
            *(uint32_t*)(smb + OFF_PL + rA * 144 + cb) = lw;
            split2(cs[t][2] * invB, cs[t][3] * invB, hw, lw);
            *(uint32_t*)(smb + OFF_PH + rB * 144 + cb) = hw;
            *(uint32_t*)(smb + OFF_PL + rB * 144 + cb) = lw;
        }
        __syncthreads();

        // ---- O_h = P @ V : warp tile m16 x n8 (nt = ntg) ----
        {
            float oc[4] = {};
#pragma unroll
            for (int ks = 0; ks < 4; ks++) {
                uint32_t ph[4], pl[4], vh[2], vl[2];
                LDSM_X4(ph, aPH + ks * 32);
                LDSM_X4(pl, aPL + ks * 32);
                LDSM_X2T(vh, aVH + ks * 1280);
                LDSM_X2T(vl, aVL + ks * 1280);
                MMA_BF16(oc, ph, vh[0], vh[1]);
                MMA_BF16(oc, ph, vl[0], vl[1]);
                MMA_BF16(oc, pl, vh[0], vh[1]);
            }
            int cc = (h * 32 + ntg * 8 + (lane & 3) * 2) * 2;
            uint32_t hw, lw;
            split2(oc[0], oc[1], hw, lw);
            *(uint32_t*)(smb + OFF_OH + rA * 400 + cc) = hw;
            *(uint32_t*)(smb + OFF_OL + rA * 400 + cc) = lw;
            split2(oc[2], oc[3], hw, lw);
            *(uint32_t*)(smb + OFF_OH + rB * 400 + cc) = hw;
            *(uint32_t*)(smb + OFF_OL + rB * 400 + cc) = lw;
        }
    }

    // ---- proj: single pass, 16 warps, m16 x n48 ----
    __syncthreads();
    {
        int boff[6];
#pragma unroll
        for (int t = 0; t < 6; t++) {
            int idx = ntg * 6 + t;
            int st  = 6 + (idx >= 12);
            int nt  = idx - 12 * (idx >= 12);
            boff[t] = st * 4608 + nt * 32 + lane;
        }
        float acc[6][4] = {};
#pragma unroll
        for (int ks = 0; ks < 12; ks++) {
            uint32_t ah[4], al[4];
            LDSM_X4(ah, aOH + ks * 32);
            LDSM_X4(al, aOL + ks * 32);
#pragma unroll
            for (int t = 0; t < 6; t++) {
                uint4 b = gW[boff[t] + ks * 384];
                MMA_BF16(acc[t], ah, b.x, b.y);
                MMA_BF16(acc[t], ah, b.z, b.w);
                MMA_BF16(acc[t], al, b.x, b.y);
            }
        }
        __syncthreads();   // X planes dead -> sPrj
#pragma unroll
        for (int t = 0; t < 6; t++) {
            int col = (ntg * 6 + t) * 8 + (lane & 3) * 2;
            *(float2*)&sPrj[rA * PJ + col] = make_float2(acc[t][0], acc[t][1]);
            *(float2*)&sPrj[rB * PJ + col] = make_float2(acc[t][2], acc[t][3]);
        }
    }
    __syncthreads();

    // ---- scatter with reverse shift (+ proj bias) ----
    float* ob = out + (size_t)bb * CCH * HH * WWD;
    for (int e = tid; e < 64 * CCH; e += THREADS) {
        int c = e >> 6, r = e & 63;
        int hh2 = wr * 8 + (r >> 3) + 4; if (hh2 >= HH)  hh2 -= HH;
        int ww2 = wc * 8 + (r & 7) + 4;  if (ww2 >= WWD) ww2 -= WWD;
        ob[(c * HH + hh2) * WWD + ww2] = sPrj[r * PJ + c] + sBias[576 + c];
    }
}

extern "C" void kernel_launch(void* const* d_in, const int* in_sizes, int n_in,
                              void* d_out, int out_size)
{
    const float* x      = (const float*)d_in[0];
    const float* qkv_w  = (const float*)d_in[1];
    const float* qkv_b  = (const float*)d_in[2];
    const float* proj_w = (const float*)d_in[3];
    const float* proj_b = (const float*)d_in[4];
    const float* tab    = (const float*)d_in[5];
    float* out = (float*)d_out;

    prepack_w<<<144, 256>>>(qkv_w, proj_w);

    cudaFuncSetAttribute(swin_mma, cudaFuncAttributeMaxDynamicSharedMemorySize, SMEM_BYTES);
    swin_mma<<<NBLK, THREADS, SMEM_BYTES>>>(x, qkv_b, proj_b, tab, out);
}

// round 14
// speedup vs baseline: 1.8066x; 1.1084x over previous
#include <cuda_runtime.h>
#include <cuda_bf16.h>
#include <cstdint>

// ShiftedWindowAttention: fully tensor-core (mma.sync bf16-split).
// One CTA per 8x8 window, 256 threads, 2 CTAs/SM. B=8,C=192,H=W=192,nh=6,hd=32.
// R13: 256-thread CTA + O-in-registers (smem 110KB) + single-barrier softmax.

#define THREADS 256
#define NBLK    4608
#define CCH     192
#define HH      192
#define WWD     192

#define XP 200        // bf16 pitch for X/O planes (400B rows)
#define PJ 196        // fp32 pitch for proj result (aliases X planes)

// smem byte offsets
#define OFF_XH   0            // 25600 ; O planes + sPrj alias this region later
#define OFF_XL   25600        // 25600
#define OFF_QH   51200        // Q/K/V bf16 planes: 64 x 80B
#define OFF_QL   56320
#define OFF_KH   61440
#define OFF_KL   66560
#define OFF_VH   71680
#define OFF_VL   76800
#define OFF_PH   81920        // P planes: 64 x 144B
#define OFF_PL   91136
#define OFF_RM   100352       // 2 x 64 f32
#define OFF_RS   100864       // 2 x 64 f32
#define OFF_TAB  101376       // 1350 f32
#define OFF_BIAS 106776       // 768 f32
#define OFF_RID  109848       // 64 int
#define SMEM_BYTES 110208

// Prepacked B fragments: [stage][ks][nt][lane] -> uint4 {bh0,bh1,bl0,bl1}.
__device__ uint4 gWB[8][12][12][32];

#define LDSM_X4(r, addr) \
    asm volatile("ldmatrix.sync.aligned.m8n8.x4.shared.b16 {%0,%1,%2,%3}, [%4];" \
        : "=r"((r)[0]), "=r"((r)[1]), "=r"((r)[2]), "=r"((r)[3]) : "r"(addr))
#define LDSM_X2(r, addr) \
    asm volatile("ldmatrix.sync.aligned.m8n8.x2.shared.b16 {%0,%1}, [%2];" \
        : "=r"((r)[0]), "=r"((r)[1]) : "r"(addr))
#define LDSM_X2T(r, addr) \
    asm volatile("ldmatrix.sync.aligned.m8n8.x2.trans.shared.b16 {%0,%1}, [%2];" \
        : "=r"((r)[0]), "=r"((r)[1]) : "r"(addr))
#define MMA_BF16(d, a, b0, b1) \
    asm volatile("mma.sync.aligned.m16n8k16.row.col.f32.bf16.bf16.f32 " \
        "{%0,%1,%2,%3}, {%4,%5,%6,%7}, {%8,%9}, {%0,%1,%2,%3};" \
        : "+f"((d)[0]), "+f"((d)[1]), "+f"((d)[2]), "+f"((d)[3]) \
        : "r"((a)[0]), "r"((a)[1]), "r"((a)[2]), "r"((a)[3]), "r"(b0), "r"(b1))

__device__ __forceinline__ uint32_t smem_u32(const void* p) {
    uint32_t a;
    asm("{ .reg .u64 t; cvta.to.shared.u64 t, %1; cvt.u32.u64 %0, t; }" : "=r"(a) : "l"(p));
    return a;
}
__device__ __forceinline__ uint32_t pk(float a, float b) {
    __nv_bfloat16 x = __float2bfloat16(a), y = __float2bfloat16(b);
    return (uint32_t)__bfloat16_as_ushort(x) | ((uint32_t)__bfloat16_as_ushort(y) << 16);
}
__device__ __forceinline__ void split2(float a, float b, uint32_t& hw, uint32_t& lw) {
    __nv_bfloat16 ha = __float2bfloat16(a), hb = __float2bfloat16(b);
    hw = (uint32_t)__bfloat16_as_ushort(ha) | ((uint32_t)__bfloat16_as_ushort(hb) << 16);
    lw = pk(a - __bfloat162float(ha), b - __bfloat162float(hb));
}

__global__ void prepack_w(const float* __restrict__ qkv_w, const float* __restrict__ proj_w)
{
    int idx = blockIdx.x * 256 + threadIdx.x;
    if (idx >= 8 * 12 * 12 * 32) return;
    int lane = idx & 31;
    int q = idx >> 5;
    int nt = q % 12, ks = (q / 12) % 12, st = q / 144;
    int n  = nt * 8 + (lane >> 2);
    int kb = ks * 16 + (lane & 3) * 2;
    const float* src;
    if (st < 6) {
        int grow = (n >> 5) * 192 + st * 32 + (n & 31);
        src = qkv_w + grow * 192;
    } else {
        src = proj_w + ((st - 6) * 96 + n) * 192;
    }
    float w0 = src[kb], w1 = src[kb + 1], w2 = src[kb + 8], w3 = src[kb + 9];
    float h0 = __bfloat162float(__float2bfloat16(w0));
    float h1 = __bfloat162float(__float2bfloat16(w1));
    float h2 = __bfloat162float(__float2bfloat16(w2));
    float h3 = __bfloat162float(__float2bfloat16(w3));
    gWB[st][ks][nt][lane] = make_uint4(pk(w0, w1), pk(w2, w3),
                                       pk(w0 - h0, w1 - h1), pk(w2 - h2, w3 - h3));
}

__global__ void __launch_bounds__(THREADS, 2)
swin_mma(const float* __restrict__ x, const float* __restrict__ qkv_b,
         const float* __restrict__ proj_b, const float* __restrict__ tab,
         float* __restrict__ out)
{
    extern __shared__ char smb[];
    const uint32_t smu = smem_u32(smb);
    __nv_bfloat16* sXH = (__nv_bfloat16*)(smb + OFF_XH);
    __nv_bfloat16* sXL = (__nv_bfloat16*)(smb + OFF_XL);
    float* sPrj = (float*)(smb + OFF_XH);
    float* sRM  = (float*)(smb + OFF_RM);
    float* sRS  = (float*)(smb + OFF_RS);
    float* sTab = (float*)(smb + OFF_TAB);
    float* sBias= (float*)(smb + OFF_BIAS);
    int*   sReg = (int*)(smb + OFF_RID);

    const int tid = threadIdx.x, warp = tid >> 5, lane = tid & 31;
    const int mt = warp & 3, g = warp >> 2;   // 4 m-tiles x 2 groups

    const int b_ = blockIdx.x;
    const int bb = b_ / 576, win = b_ - bb * 576;
    const int wr = win / 24, wc = win - wr * 24;

    const uint4* __restrict__ gW = &gWB[0][0][0][0];

    const uint32_t aXH = smu + OFF_XH + (mt * 16 + (lane & 15)) * 400 + ((lane >> 4) << 4);
    const uint32_t aXL = aXH + 25600;
    const uint32_t aQH = smu + OFF_QH + (mt * 16 + (lane & 15)) * 80 + ((lane >> 4) << 4);
    const uint32_t aQL = aQH + 5120;
    const uint32_t aKH = smu + OFF_KH + (lane & 7) * 80 + (((lane >> 3) & 1) << 4);
    const uint32_t aKL = aKH + 5120;
    const uint32_t aPH = smu + OFF_PH + (mt * 16 + (lane & 15)) * 144 + ((lane >> 4) << 4);
    const uint32_t aPL = aPH + 9216;
    const uint32_t aVH = smu + OFF_VH + (lane & 15) * 80;
    const uint32_t aVL = aVH + 5120;

    // ---- tables / bias / region ids ----
    for (int i = tid; i < 1350; i += THREADS) sTab[i] = tab[i];
    for (int i = tid; i < 768; i += THREADS) sBias[i] = (i < 576) ? qkv_b[i] : proj_b[i - 576];
    if (tid < 64) {
        int ii = tid >> 3, jj = tid & 7;
        int hs = wr * 8 + ii, ws = wc * 8 + jj;
        sReg[tid] = (hs < 184 ? 0 : (hs < 188 ? 1 : 2)) * 3 + (ws < 184 ? 0 : (ws < 188 ? 1 : 2));
    }

    // ---- gather shifted window -> X hi/lo bf16 planes ----
    const float* xb = x + (size_t)bb * CCH * HH * WWD;
    for (int e = tid; e < 64 * CCH; e += THREADS) {
        int c = e >> 6, r = e & 63;
        int hh2 = wr * 8 + (r >> 3) + 4; if (hh2 >= HH)  hh2 -= HH;
        int ww2 = wc * 8 + (r & 7) + 4;  if (ww2 >= WWD) ww2 -= WWD;
        float v = xb[(c * HH + hh2) * WWD + ww2];
        __nv_bfloat16 hi = __float2bfloat16(v);
        sXH[r * XP + c] = hi;
        sXL[r * XP + c] = __float2bfloat16(v - __bfloat162float(hi));
    }

    const float scale = 0.17677669529663687f;
    const int rA = mt * 16 + (lane >> 2), rB = rA + 8;

    float og[6][2][4];   // persistent attention-output fragments

#pragma unroll
    for (int h = 0; h < 6; h++) {
        __syncthreads();   // QKV/P planes free; gather visible at h=0

        // ---- QKV GEMM: 8 warps m16n48 ----
        {
            const uint4* bw = gW + h * 4608 + g * 192 + lane;
            float acc[6][4] = {};
#pragma unroll
            for (int ks = 0; ks < 12; ks++) {
                uint32_t ah[4], al[4];
                LDSM_X4(ah, aXH + ks * 32);
                LDSM_X4(al, aXL + ks * 32);
#pragma unroll
                for (int t = 0; t < 6; t++) {
                    uint4 b = bw[ks * 384 + t * 32];
                    MMA_BF16(acc[t], ah, b.x, b.y);
                    MMA_BF16(acc[t], ah, b.z, b.w);
                    MMA_BF16(acc[t], al, b.x, b.y);
                }
            }
#pragma unroll
            for (int t = 0; t < 6; t++) {
                int gc = (g * 6 + t) * 8 + (lane & 3) * 2;
                int ofs; int lc; float b0_, b1_; float m = 1.f;
                if (gc < 32)      { ofs = OFF_QH; lc = gc;      b0_ = sBias[h*32+lc];     b1_ = sBias[h*32+lc+1];     m = scale; }
                else if (gc < 64) { ofs = OFF_KH; lc = gc - 32; b0_ = sBias[192+h*32+lc]; b1_ = sBias[192+h*32+lc+1]; }
                else              { ofs = OFF_VH; lc = gc - 64; b0_ = sBias[384+h*32+lc]; b1_ = sBias[384+h*32+lc+1]; }
                uint32_t hw, lw;
                split2((acc[t][0] + b0_) * m, (acc[t][1] + b1_) * m, hw, lw);
                *(uint32_t*)(smb + ofs + rA * 80 + lc * 2) = hw;
                *(uint32_t*)(smb + ofs + 5120 + rA * 80 + lc * 2) = lw;
                split2((acc[t][2] + b0_) * m, (acc[t][3] + b1_) * m, hw, lw);
                *(uint32_t*)(smb + ofs + rB * 80 + lc * 2) = hw;
                *(uint32_t*)(smb + ofs + 5120 + rB * 80 + lc * 2) = lw;
            }
        }
        __syncthreads();

        // ---- scores: warp m16 x n32 (n8-tiles 4g..4g+3) ----
        float cs[4][4] = {};
#pragma unroll
        for (int ks = 0; ks < 2; ks++) {
            uint32_t qh[4], ql[4];
            LDSM_X4(qh, aQH + ks * 32);
            LDSM_X4(ql, aQL + ks * 32);
#pragma unroll
            for (int t = 0; t < 4; t++) {
                uint32_t kh[2], kl[2];
                LDSM_X2(kh, aKH + (g * 4 + t) * 640 + ks * 32);
                LDSM_X2(kl, aKL + (g * 4 + t) * 640 + ks * 32);
                MMA_BF16(cs[t], qh, kh[0], kh[1]);
                MMA_BF16(cs[t], qh, kl[0], kl[1]);
                MMA_BF16(cs[t], ql, kh[0], kh[1]);
            }
        }

        // ---- bias + mask ----
        {
            int regA = sReg[rA], regB = sReg[rB];
            int i1A = rA >> 3, j1A = rA & 7, i1B = rB >> 3, j1B = rB & 7;
#pragma unroll
            for (int t = 0; t < 4; t++) {
#pragma unroll
                for (int par = 0; par < 2; par++) {
                    int m = g * 32 + t * 8 + (lane & 3) * 2 + par;
                    int i2 = m >> 3, j2 = m & 7, rm = sReg[m];
                    cs[t][par]     += sTab[((i1A - i2 + 7) * 15 + (j1A - j2 + 7)) * 6 + h]
                                    + (rm == regA ? 0.f : -100.f);
                    cs[t][2 + par] += sTab[((i1B - i2 + 7) * 15 + (j1B - j2 + 7)) * 6 + h]
                                    + (rm == regB ? 0.f : -100.f);
                }
            }
        }

        // ---- softmax: local max/exp/sum, ONE barrier, rescale ----
        float mA = fmaxf(fmaxf(cs[0][0], cs[0][1]), fmaxf(cs[1][0], cs[1][1]));
        mA = fmaxf(mA, fmaxf(fmaxf(cs[2][0], cs[2][1]), fmaxf(cs[3][0], cs[3][1])));
        float mB = fmaxf(fmaxf(cs[0][2], cs[0][3]), fmaxf(cs[1][2], cs[1][3]));
        mB = fmaxf(mB, fmaxf(fmaxf(cs[2][2], cs[2][3]), fmaxf(cs[3][2], cs[3][3])));
        mA = fmaxf(mA, __shfl_xor_sync(0xffffffffu, mA, 1));
        mA = fmaxf(mA, __shfl_xor_sync(0xffffffffu, mA, 2));
        mB = fmaxf(mB, __shfl_xor_sync(0xffffffffu, mB, 1));
        mB = fmaxf(mB, __shfl_xor_sync(0xffffffffu, mB, 2));
        float sA = 0.f, sB = 0.f;
#pragma unroll
        for (int t = 0; t < 4; t++) {
            cs[t][0] = __expf(cs[t][0] - mA); cs[t][1] = __expf(cs[t][1] - mA);
            cs[t][2] = __expf(cs[t][2] - mB); cs[t][3] = __expf(cs[t][3] - mB);
            sA += cs[t][0] + cs[t][1];
            sB += cs[t][2] + cs[t][3];
        }
        sA += __shfl_xor_sync(0xffffffffu, sA, 1);
        sA += __shfl_xor_sync(0xffffffffu, sA, 2);
        sB += __shfl_xor_sync(0xffffffffu, sB, 1);
        sB += __shfl_xor_sync(0xffffffffu, sB, 2);
        if ((lane & 3) == 0) {
            sRM[g * 64 + rA] = mA; sRM[g * 64 + rB] = mB;
            sRS[g * 64 + rA] = sA; sRS[g * 64 + rB] = sB;
        }
        __syncthreads();
        float fA, fB;
        {
            float m0 = sRM[rA], m1 = sRM[64 + rA];
            float gm = fmaxf(m0, m1);
            float st = sRS[rA] * __expf(m0 - gm) + sRS[64 + rA] * __expf(m1 - gm);
            fA = __expf(mA - gm) / st;
            m0 = sRM[rB]; m1 = sRM[64 + rB];
            gm = fmaxf(m0, m1);
            st = sRS[rB] * __expf(m0 - gm) + sRS[64 + rB] * __expf(m1 - gm);
            fB = __expf(mB - gm) / st;
        }

        // ---- write P hi/lo planes ----
#pragma unroll
        for (int t = 0; t < 4; t++) {
            int cb = (g * 32 + t * 8 + (lane & 3) * 2) * 2;
            uint32_t hw, lw;
            split2(cs[t][0] * fA, cs[t][1] * fA, hw, lw);
            *(uint32_t*)(smb + OFF_PH + rA * 144 + cb) = hw;
            *(uint32_t*)(smb + OFF_PL + rA * 144 + cb) = lw;
            split2(cs[t][2] * fB, cs[t][3] * fB, hw, lw);
            *(uint32_t*)(smb + OFF_PH + rB * 144 + cb) = hw;
            *(uint32_t*)(smb + OFF_PL + rB * 144 + cb) = lw;
        }
        __syncthreads();

        // ---- O_h = P @ V -> registers (2 n-tiles: 2g, 2g+1) ----
#pragma unroll
        for (int j = 0; j < 2; j++)
#pragma unroll
            for (int i = 0; i < 4; i++) og[h][j][i] = 0.f;
#pragma unroll
        for (int ks = 0; ks < 4; ks++) {
            uint32_t ph[4], pl[4];
            LDSM_X4(ph, aPH + ks * 32);
            LDSM_X4(pl, aPL + ks * 32);
#pragma unroll
            for (int j = 0; j < 2; j++) {
                uint32_t vh[2], vl[2];
                LDSM_X2T(vh, aVH + (g * 2 + j) * 16 + ks * 1280);
                LDSM_X2T(vl, aVL + (g * 2 + j) * 16 + ks * 1280);
                MMA_BF16(og[h][j], ph, vh[0], vh[1]);
                MMA_BF16(og[h][j], ph, vl[0], vl[1]);
                MMA_BF16(og[h][j], pl, vh[0], vh[1]);
            }
        }
    }

    // ---- spill O regs -> hi/lo planes in X region (X dead) ----
#pragma unroll
    for (int h = 0; h < 6; h++)
#pragma unroll
        for (int j = 0; j < 2; j++) {
            int cc = (h * 32 + (g * 2 + j) * 8 + (lane & 3) * 2) * 2;
            uint32_t hw, lw;
            split2(og[h][j][0], og[h][j][1], hw, lw);
            *(uint32_t*)(smb + OFF_XH + rA * 400 + cc) = hw;
            *(uint32_t*)(smb + OFF_XL + rA * 400 + cc) = lw;
            split2(og[h][j][2], og[h][j][3], hw, lw);
            *(uint32_t*)(smb + OFF_XH + rB * 400 + cc) = hw;
            *(uint32_t*)(smb + OFF_XL + rB * 400 + cc) = lw;
        }
    __syncthreads();

    // ---- proj: 8 warps m16 x n96 (stage 6+g) ----
    {
        const uint4* bw = gW + (6 + g) * 4608 + lane;
        float acc[12][4] = {};
#pragma unroll
        for (int ks = 0; ks < 12; ks++) {
            uint32_t ah[4], al[4];
            LDSM_X4(ah, aXH + ks * 32);
            LDSM_X4(al, aXL + ks * 32);
#pragma unroll
            for (int t = 0; t < 12; t++) {
                uint4 b = bw[ks * 384 + t * 32];
                MMA_BF16(acc[t], ah, b.x, b.y);
                MMA_BF16(acc[t], ah, b.z, b.w);
                MMA_BF16(acc[t], al, b.x, b.y);
            }
        }
        __syncthreads();   // O planes consumed -> region becomes sPrj
#pragma unroll
        for (int t = 0; t < 12; t++) {
            int col = (g * 12 + t) * 8 + (lane & 3) * 2;
            *(float2*)&sPrj[rA * PJ + col] = make_float2(acc[t][0], acc[t][1]);
            *(float2*)&sPrj[rB * PJ + col] = make_float2(acc[t][2], acc[t][3]);
        }
    }
    __syncthreads();

    // ---- scatter with reverse shift (+ proj bias) ----
    float* ob = out + (size_t)bb * CCH * HH * WWD;
    for (int e = tid; e < 64 * CCH; e += THREADS) {
        int c = e >> 6, r = e & 63;
        int hh2 = wr * 8 + (r >> 3) + 4; if (hh2 >= HH)  hh2 -= HH;
        int ww2 = wc * 8 + (r & 7) + 4;  if (ww2 >= WWD) ww2 -= WWD;
        ob[(c * HH + hh2) * WWD + ww2] = sPrj[r * PJ + c] + sBias[576 + c];
    }
}

extern "C" void kernel_launch(void* const* d_in, const int* in_sizes, int n_in,
                              void* d_out, int out_size)
{
    const float* x      = (const float*)d_in[0];
    const float* qkv_w  = (const float*)d_in[1];
    const float* qkv_b  = (const float*)d_in[2];
    const float* proj_w = (const float*)d_in[3];
    const float* proj_b = (const float*)d_in[4];
    const float* tab    = (const float*)d_in[5];
    float* out = (float*)d_out;

    prepack_w<<<144, 256>>>(qkv_w, proj_w);

    cudaFuncSetAttribute(swin_mma, cudaFuncAttributeMaxDynamicSharedMemorySize, SMEM_BYTES);
    swin_mma<<<NBLK, THREADS, SMEM_BYTES>>>(x, qkv_b, proj_b, tab, out);
}

// round 15
// speedup vs baseline: 1.8764x; 1.0387x over previous
#include <cuda_runtime.h>
#include <cuda_bf16.h>
#include <cstdint>

// ShiftedWindowAttention: fully tensor-core (mma.sync bf16-split).
// One CTA per 8x8 window, 256 threads, 2 CTAs/SM. B=8,C=192,H=W=192,nh=6,hd=32.
// R14: P stays in registers (score-frag -> A-frag reuse), warp-owns-row softmax
//      (no barriers), 2 barriers/head, smem 91KB.

#define THREADS 256
#define NBLK    4608
#define CCH     192
#define HH      192
#define WWD     192

#define XP 200        // bf16 pitch for X/O planes (400B rows)
#define PJ 196        // fp32 pitch for proj result (aliases X planes)

// smem byte offsets
#define OFF_XH   0            // 25600 ; O planes + sPrj alias this region later
#define OFF_XL   25600
#define OFF_QH   51200        // Q/K/V bf16 planes: 64 x 80B
#define OFF_QL   56320
#define OFF_KH   61440
#define OFF_KL   66560
#define OFF_VH   71680
#define OFF_VL   76800
#define OFF_TAB  81920        // 1350 f32
#define OFF_BIAS 87320        // 768 f32
#define OFF_RID  90392        // 64 int
#define SMEM_BYTES 90656

// Prepacked B fragments: [stage][ks][nt][lane] -> uint4 {bh0,bh1,bl0,bl1}.
__device__ uint4 gWB[8][12][12][32];

#define LDSM_X4(r, addr) \
    asm volatile("ldmatrix.sync.aligned.m8n8.x4.shared.b16 {%0,%1,%2,%3}, [%4];" \
        : "=r"((r)[0]), "=r"((r)[1]), "=r"((r)[2]), "=r"((r)[3]) : "r"(addr))
#define LDSM_X2(r, addr) \
    asm volatile("ldmatrix.sync.aligned.m8n8.x2.shared.b16 {%0,%1}, [%2];" \
        : "=r"((r)[0]), "=r"((r)[1]) : "r"(addr))
#define LDSM_X2T(r, addr) \
    asm volatile("ldmatrix.sync.aligned.m8n8.x2.trans.shared.b16 {%0,%1}, [%2];" \
        : "=r"((r)[0]), "=r"((r)[1]) : "r"(addr))
#define MMA_BF16(d, a, b0, b1) \
    asm volatile("mma.sync.aligned.m16n8k16.row.col.f32.bf16.bf16.f32 " \
        "{%0,%1,%2,%3}, {%4,%5,%6,%7}, {%8,%9}, {%0,%1,%2,%3};" \
        : "+f"((d)[0]), "+f"((d)[1]), "+f"((d)[2]), "+f"((d)[3]) \
        : "r"((a)[0]), "r"((a)[1]), "r"((a)[2]), "r"((a)[3]), "r"(b0), "r"(b1))

__device__ __forceinline__ uint32_t smem_u32(const void* p) {
    uint32_t a;
    asm("{ .reg .u64 t; cvta.to.shared.u64 t, %1; cvt.u32.u64 %0, t; }" : "=r"(a) : "l"(p));
    return a;
}
__device__ __forceinline__ uint32_t pk(float a, float b) {
    __nv_bfloat16 x = __float2bfloat16(a), y = __float2bfloat16(b);
    return (uint32_t)__bfloat16_as_ushort(x) | ((uint32_t)__bfloat16_as_ushort(y) << 16);
}
__device__ __forceinline__ void split2(float a, float b, uint32_t& hw, uint32_t& lw) {
    __nv_bfloat16 ha = __float2bfloat16(a), hb = __float2bfloat16(b);
    hw = (uint32_t)__bfloat16_as_ushort(ha) | ((uint32_t)__bfloat16_as_ushort(hb) << 16);
    lw = pk(a - __bfloat162float(ha), b - __bfloat162float(hb));
}

__global__ void prepack_w(const float* __restrict__ qkv_w, const float* __restrict__ proj_w)
{
    int idx = blockIdx.x * 256 + threadIdx.x;
    if (idx >= 8 * 12 * 12 * 32) return;
    int lane = idx & 31;
    int q = idx >> 5;
    int nt = q % 12, ks = (q / 12) % 12, st = q / 144;
    int n  = nt * 8 + (lane >> 2);
    int kb = ks * 16 + (lane & 3) * 2;
    const float* src;
    if (st < 6) {
        int grow = (n >> 5) * 192 + st * 32 + (n & 31);
        src = qkv_w + grow * 192;
    } else {
        src = proj_w + ((st - 6) * 96 + n) * 192;
    }
    float w0 = src[kb], w1 = src[kb + 1], w2 = src[kb + 8], w3 = src[kb + 9];
    float h0 = __bfloat162float(__float2bfloat16(w0));
    float h1 = __bfloat162float(__float2bfloat16(w1));
    float h2 = __bfloat162float(__float2bfloat16(w2));
    float h3 = __bfloat162float(__float2bfloat16(w3));
    gWB[st][ks][nt][lane] = make_uint4(pk(w0, w1), pk(w2, w3),
                                       pk(w0 - h0, w1 - h1), pk(w2 - h2, w3 - h3));
}

__global__ void __launch_bounds__(THREADS, 2)
swin_mma(const float* __restrict__ x, const float* __restrict__ qkv_b,
         const float* __restrict__ proj_b, const float* __restrict__ tab,
         float* __restrict__ out)
{
    extern __shared__ char smb[];
    const uint32_t smu = smem_u32(smb);
    __nv_bfloat16* sXH = (__nv_bfloat16*)(smb + OFF_XH);
    __nv_bfloat16* sXL = (__nv_bfloat16*)(smb + OFF_XL);
    float* sPrj = (float*)(smb + OFF_XH);
    float* sTab = (float*)(smb + OFF_TAB);
    float* sBias= (float*)(smb + OFF_BIAS);
    int*   sReg = (int*)(smb + OFF_RID);

    const int tid = threadIdx.x, warp = tid >> 5, lane = tid & 31;
    const int mt = warp & 3, g = warp >> 2;   // 4 m-tiles x 2 groups

    const int b_ = blockIdx.x;
    const int bb = b_ / 576, win = b_ - bb * 576;
    const int wr = win / 24, wc = win - wr * 24;

    const uint4* __restrict__ gW = &gWB[0][0][0][0];

    const uint32_t aXH = smu + OFF_XH + (mt * 16 + (lane & 15)) * 400 + ((lane >> 4) << 4);
    const uint32_t aXL = aXH + 25600;
    const uint32_t aQH = smu + OFF_QH + (mt * 16 + (lane & 15)) * 80 + ((lane >> 4) << 4);
    const uint32_t aQL = aQH + 5120;
    const uint32_t aKH = smu + OFF_KH + (lane & 7) * 80 + (((lane >> 3) & 1) << 4);
    const uint32_t aKL = aKH + 5120;
    const uint32_t aVH = smu + OFF_VH + (lane & 15) * 80;
    const uint32_t aVL = aVH + 5120;

    // ---- tables / bias / region ids ----
    for (int i = tid; i < 1350; i += THREADS) sTab[i] = tab[i];
    for (int i = tid; i < 768; i += THREADS) sBias[i] = (i < 576) ? qkv_b[i] : proj_b[i - 576];
    if (tid < 64) {
        int ii = tid >> 3, jj = tid & 7;
        int hs = wr * 8 + ii, ws = wc * 8 + jj;
        sReg[tid] = (hs < 184 ? 0 : (hs < 188 ? 1 : 2)) * 3 + (ws < 184 ? 0 : (ws < 188 ? 1 : 2));
    }

    // ---- gather shifted window -> X hi/lo bf16 planes ----
    const float* xb = x + (size_t)bb * CCH * HH * WWD;
    for (int e = tid; e < 64 * CCH; e += THREADS) {
        int c = e >> 6, r = e & 63;
        int hh2 = wr * 8 + (r >> 3) + 4; if (hh2 >= HH)  hh2 -= HH;
        int ww2 = wc * 8 + (r & 7) + 4;  if (ww2 >= WWD) ww2 -= WWD;
        float v = xb[(c * HH + hh2) * WWD + ww2];
        __nv_bfloat16 hi = __float2bfloat16(v);
        sXH[r * XP + c] = hi;
        sXL[r * XP + c] = __float2bfloat16(v - __bfloat162float(hi));
    }

    const float scale = 0.17677669529663687f;
    const int rA = mt * 16 + (lane >> 2), rB = rA + 8;

    float og[6][2][4];   // persistent attention-output fragments

#pragma unroll
    for (int h = 0; h < 6; h++) {
        __syncthreads();   // QKV planes free (prev head's V consumed); gather visible at h=0

        // ---- QKV GEMM: 8 warps m16n48 ----
        {
            const uint4* bw = gW + h * 4608 + g * 192 + lane;
            float acc[6][4] = {};
#pragma unroll
            for (int ks = 0; ks < 12; ks++) {
                uint32_t ah[4], al[4];
                LDSM_X4(ah, aXH + ks * 32);
                LDSM_X4(al, aXL + ks * 32);
#pragma unroll
                for (int t = 0; t < 6; t++) {
                    uint4 b = bw[ks * 384 + t * 32];
                    MMA_BF16(acc[t], ah, b.x, b.y);
                    MMA_BF16(acc[t], ah, b.z, b.w);
                    MMA_BF16(acc[t], al, b.x, b.y);
                }
            }
#pragma unroll
            for (int t = 0; t < 6; t++) {
                int gc = (g * 6 + t) * 8 + (lane & 3) * 2;
                int ofs; int lc; float b0_, b1_; float m = 1.f;
                if (gc < 32)      { ofs = OFF_QH; lc = gc;      b0_ = sBias[h*32+lc];     b1_ = sBias[h*32+lc+1];     m = scale; }
                else if (gc < 64) { ofs = OFF_KH; lc = gc - 32; b0_ = sBias[192+h*32+lc]; b1_ = sBias[192+h*32+lc+1]; }
                else              { ofs = OFF_VH; lc = gc - 64; b0_ = sBias[384+h*32+lc]; b1_ = sBias[384+h*32+lc+1]; }
                uint32_t hw, lw;
                split2((acc[t][0] + b0_) * m, (acc[t][1] + b1_) * m, hw, lw);
                *(uint32_t*)(smb + ofs + rA * 80 + lc * 2) = hw;
                *(uint32_t*)(smb + ofs + 5120 + rA * 80 + lc * 2) = lw;
                split2((acc[t][2] + b0_) * m, (acc[t][3] + b1_) * m, hw, lw);
                *(uint32_t*)(smb + ofs + rB * 80 + lc * 2) = hw;
                *(uint32_t*)(smb + ofs + 5120 + rB * 80 + lc * 2) = lw;
            }
        }
        __syncthreads();

        // ---- scores: each warp computes its FULL rows (m16 x n64) ----
        float cs[8][4] = {};
#pragma unroll
        for (int ks = 0; ks < 2; ks++) {
            uint32_t qh[4], ql[4];
            LDSM_X4(qh, aQH + ks * 32);
            LDSM_X4(ql, aQL + ks * 32);
#pragma unroll
            for (int t = 0; t < 8; t++) {
                uint32_t kh[2], kl[2];
                LDSM_X2(kh, aKH + t * 640 + ks * 32);
                LDSM_X2(kl, aKL + t * 640 + ks * 32);
                MMA_BF16(cs[t], qh, kh[0], kh[1]);
                MMA_BF16(cs[t], qh, kl[0], kl[1]);
                MMA_BF16(cs[t], ql, kh[0], kh[1]);
            }
        }

        // ---- bias + mask ----
        {
            int regA = sReg[rA], regB = sReg[rB];
            int i1A = rA >> 3, j1A = rA & 7, i1B = rB >> 3, j1B = rB & 7;
#pragma unroll
            for (int t = 0; t < 8; t++) {
#pragma unroll
                for (int par = 0; par < 2; par++) {
                    int m = t * 8 + (lane & 3) * 2 + par;
                    int i2 = m >> 3, j2 = m & 7, rm = sReg[m];
                    cs[t][par]     += sTab[((i1A - i2 + 7) * 15 + (j1A - j2 + 7)) * 6 + h]
                                    + (rm == regA ? 0.f : -100.f);
                    cs[t][2 + par] += sTab[((i1B - i2 + 7) * 15 + (j1B - j2 + 7)) * 6 + h]
                                    + (rm == regB ? 0.f : -100.f);
                }
            }
        }

        // ---- softmax fully in-warp (rows complete): quad shfl only ----
        {
            float mA = -1e30f, mB = -1e30f;
#pragma unroll
            for (int t = 0; t < 8; t++) {
                mA = fmaxf(mA, fmaxf(cs[t][0], cs[t][1]));
                mB = fmaxf(mB, fmaxf(cs[t][2], cs[t][3]));
            }
            mA = fmaxf(mA, __shfl_xor_sync(0xffffffffu, mA, 1));
            mA = fmaxf(mA, __shfl_xor_sync(0xffffffffu, mA, 2));
            mB = fmaxf(mB, __shfl_xor_sync(0xffffffffu, mB, 1));
            mB = fmaxf(mB, __shfl_xor_sync(0xffffffffu, mB, 2));
            float sA = 0.f, sB = 0.f;
#pragma unroll
            for (int t = 0; t < 8; t++) {
                cs[t][0] = __expf(cs[t][0] - mA); cs[t][1] = __expf(cs[t][1] - mA);
                cs[t][2] = __expf(cs[t][2] - mB); cs[t][3] = __expf(cs[t][3] - mB);
                sA += cs[t][0] + cs[t][1];
                sB += cs[t][2] + cs[t][3];
            }
            sA += __shfl_xor_sync(0xffffffffu, sA, 1);
            sA += __shfl_xor_sync(0xffffffffu, sA, 2);
            sB += __shfl_xor_sync(0xffffffffu, sB, 1);
            sB += __shfl_xor_sync(0xffffffffu, sB, 2);
            float invA = 1.f / sA, invB = 1.f / sB;
#pragma unroll
            for (int t = 0; t < 8; t++) {
                cs[t][0] *= invA; cs[t][1] *= invA;
                cs[t][2] *= invB; cs[t][3] *= invB;
            }
        }

        // ---- O_h = P @ V : P frags direct from score frags (no smem) ----
#pragma unroll
        for (int j = 0; j < 2; j++)
#pragma unroll
            for (int i = 0; i < 4; i++) og[h][j][i] = 0.f;
#pragma unroll
        for (int kc = 0; kc < 4; kc++) {
            uint32_t ph[4], pl[4];
            split2(cs[2*kc][0],   cs[2*kc][1],   ph[0], pl[0]);
            split2(cs[2*kc][2],   cs[2*kc][3],   ph[1], pl[1]);
            split2(cs[2*kc+1][0], cs[2*kc+1][1], ph[2], pl[2]);
            split2(cs[2*kc+1][2], cs[2*kc+1][3], ph[3], pl[3]);
#pragma unroll
            for (int j = 0; j < 2; j++) {
                uint32_t vh[2], vl[2];
                LDSM_X2T(vh, aVH + (g * 2 + j) * 16 + kc * 1280);
                LDSM_X2T(vl, aVL + (g * 2 + j) * 16 + kc * 1280);
                MMA_BF16(og[h][j], ph, vh[0], vh[1]);
                MMA_BF16(og[h][j], ph, vl[0], vl[1]);
                MMA_BF16(og[h][j], pl, vh[0], vh[1]);
            }
        }
    }

    // ---- spill O regs -> hi/lo planes in X region (X dead) ----
    __syncthreads();
#pragma unroll
    for (int h = 0; h < 6; h++)
#pragma unroll
        for (int j = 0; j < 2; j++) {
            int cc = (h * 32 + (g * 2 + j) * 8 + (lane & 3) * 2) * 2;
            uint32_t hw, lw;
            split2(og[h][j][0], og[h][j][1], hw, lw);
            *(uint32_t*)(smb + OFF_XH + rA * 400 + cc) = hw;
            *(uint32_t*)(smb + OFF_XL + rA * 400 + cc) = lw;
            split2(og[h][j][2], og[h][j][3], hw, lw);
            *(uint32_t*)(smb + OFF_XH + rB * 400 + cc) = hw;
            *(uint32_t*)(smb + OFF_XL + rB * 400 + cc) = lw;
        }
    __syncthreads();

    // ---- proj: 8 warps m16 x n96 (stage 6+g) ----
    {
        const uint4* bw = gW + (6 + g) * 4608 + lane;
        float acc[12][4] = {};
#pragma unroll
        for (int ks = 0; ks < 12; ks++) {
            uint32_t ah[4], al[4];
            LDSM_X4(ah, aXH + ks * 32);
            LDSM_X4(al, aXL + ks * 32);
#pragma unroll
            for (int t = 0; t < 12; t++) {
                uint4 b = bw[ks * 384 + t * 32];
                MMA_BF16(acc[t], ah, b.x, b.y);
                MMA_BF16(acc[t], ah, b.z, b.w);
                MMA_BF16(acc[t], al, b.x, b.y);
            }
        }
        __syncthreads();   // O planes consumed -> region becomes sPrj
#pragma unroll
        for (int t = 0; t < 12; t++) {
            int col = (g * 12 + t) * 8 + (lane & 3) * 2;
            *(float2*)&sPrj[rA * PJ + col] = make_float2(acc[t][0], acc[t][1]);
            *(float2*)&sPrj[rB * PJ + col] = make_float2(acc[t][2], acc[t][3]);
        }
    }
    __syncthreads();

    // ---- scatter with reverse shift (+ proj bias) ----
    float* ob = out + (size_t)bb * CCH * HH * WWD;
    for (int e = tid; e < 64 * CCH; e += THREADS) {
        int c = e >> 6, r = e & 63;
        int hh2 = wr * 8 + (r >> 3) + 4; if (hh2 >= HH)  hh2 -= HH;
        int ww2 = wc * 8 + (r & 7) + 4;  if (ww2 >= WWD) ww2 -= WWD;
        ob[(c * HH + hh2) * WWD + ww2] = sPrj[r * PJ + c] + sBias[576 + c];
    }
}

extern "C" void kernel_launch(void* const* d_in, const int* in_sizes, int n_in,
                              void* d_out, int out_size)
{
    const float* x      = (const float*)d_in[0];
    const float* qkv_w  = (const float*)d_in[1];
    const float* qkv_b  = (const float*)d_in[2];
    const float* proj_w = (const float*)d_in[3];
    const float* proj_b = (const float*)d_in[4];
    const float* tab    = (const float*)d_in[5];
    float* out = (float*)d_out;

    prepack_w<<<144, 256>>>(qkv_w, proj_w);

    cudaFuncSetAttribute(swin_mma, cudaFuncAttributeMaxDynamicSharedMemorySize, SMEM_BYTES);
    swin_mma<<<NBLK, THREADS, SMEM_BYTES>>>(x, qkv_b, proj_b, tab, out);
}